// round 5
// baseline (speedup 1.0000x reference)
#include <cuda_runtime.h>
#include <cuda_bf16.h>

// Problem constants (fixed by setup_inputs): B=2, N=1024, D_IN=D_OUT=8, C=32
#define NPT   1024
#define NC    32
#define TA    16        // a's per block (one warp per a)
#define TB    32        // b-tile per smem stage
#define NSPLIT 2        // b-range split for occupancy
#define BRANGE (NPT / NSPLIT)
#define NTHREADS 512
#define CW    8         // c-window width

typedef unsigned long long ull;

// Scratch: pre-contracted P[z][b][c][i], i fastest. Up to 4 batches.
__device__ float g_P[4 * NPT * NC * 8];

// ---------------------------------------------------------------------------
// Kernel 1: P[z,b,c,i] = sum_j W[c,i,j] * feat[z,b,j]
// ---------------------------------------------------------------------------
__global__ __launch_bounds__(256, 4)
void compute_P_kernel(const float* __restrict__ features,  // [B,N,8]
                      const float* __restrict__ Wm,        // [32,8,8]
                      float* __restrict__ P)
{
    __shared__ float sW[NC * 64];
    __shared__ float sf[8];
    const int zb  = blockIdx.x;
    const int tid = threadIdx.x;

    for (int i = tid; i < NC * 64; i += 256) sW[i] = Wm[i];
    if (tid < 8) sf[tid] = features[zb * 8 + tid];
    __syncthreads();

    const int c = tid >> 3, i = tid & 7;
    const float* wr = &sW[c * 64 + i * 8];
    float p = 0.0f;
    #pragma unroll
    for (int j = 0; j < 8; j++) p += wr[j] * sf[j];
    P[(size_t)zb * 256 + tid] = p;
}

// ---------------------------------------------------------------------------
// Kernel 2: windowed radial conv over a b-subrange, red.global.add epilogue.
// Block = (z, 16 a's, b-half). Warp = one a. Lane = b4(=lane>>3) x c_off(=lane&7).
// ---------------------------------------------------------------------------
__global__ __launch_bounds__(NTHREADS, 2)
void conv_window_kernel(const float* __restrict__ geometry,  // [B,N,3]
                        const float* __restrict__ P,         // [B,N,32,8]
                        const int*   __restrict__ n_norm_p,
                        float* __restrict__ out,             // [B,N,8]
                        int N)
{
    __shared__ float  s_P[TB * 256];        // 32 KB: P tile [b][c][i]
    __shared__ float2 s_meta[TA * TB];      // {t - c0f, int_as_float(b*1024 + c0*32)}

    const int tid   = threadIdx.x;
    const int w     = tid >> 5;              // warp = a_local
    const int lane  = tid & 31;
    const int b4    = lane >> 3;             // which of 4 b's in a group
    const int c_off = lane & 7;              // window center offset
    const int z     = blockIdx.y;
    const int a0    = blockIdx.x * TA;
    const int bbase = blockIdx.z * BRANGE;

    const float inv_width = (float)(NC - 1) / 3.5f;
    const float coff_f    = (float)c_off;
    const float NLOG2E    = -1.4426950408889634f;

    const float* geomz = geometry + (size_t)z * N * 3;
    const float* Pz    = P + (size_t)z * N * 256;

    // Meta-pass identity: thread = pair (am = tid>>5, bb = tid&31)
    const int am = tid >> 5;
    const int bb = tid & 31;
    const float ax = geomz[(a0 + am) * 3 + 0];
    const float ay = geomz[(a0 + am) * 3 + 1];
    const float az = geomz[(a0 + am) * 3 + 2];

    // Per-lane base byte address into s_P (adds c_off*32 for the window row)
    const char* sPb = (const char*)s_P + c_off * 32;

    ull acc0 = 0ull, acc1 = 0ull, acc2 = 0ull, acc3 = 0ull;  // i-pairs 0..3

    for (int t0 = 0; t0 < BRANGE; t0 += TB) {
        __syncthreads();   // previous tile fully consumed

        // Stage P tile: TB*256 floats = 2048 float4, 4 per thread
        {
            const float4* src = (const float4*)(Pz + (size_t)(bbase + t0) * 256);
            float4* dst = (float4*)s_P;
            #pragma unroll
            for (int k = 0; k < 4; k++)
                dst[tid + k * NTHREADS] = src[tid + k * NTHREADS];
        }
        // Meta: one (a,b) pair per thread
        {
            const int bg = bbase + t0 + bb;
            float dx = ax - __ldg(&geomz[bg * 3 + 0]);
            float dy = ay - __ldg(&geomz[bg * 3 + 1]);
            float dz = az - __ldg(&geomz[bg * 3 + 2]);
            float d  = sqrtf(dx * dx + dy * dy + dz * dz + 1e-12f);
            float t  = d * inv_width;
            float c0f = fmaxf(fminf(floorf(t) - 3.0f, (float)(NC - CW)), 0.0f);
            int   off = bb * 1024 + (int)c0f * 32;
            s_meta[am * TB + bb] = make_float2(t - c0f, __int_as_float(off));
        }
        __syncthreads();

        // Hot loop: 8 groups of 4 b's; each lane owns one (b, center) combo
        const float2* mw = s_meta + w * TB;
        #pragma unroll
        for (int g = 0; g < TB / 4; g++) {
            float2 mm = mw[g * 4 + b4];                 // per-lane LDS.64 (4 distinct, bcast)
            float arg = mm.x - coff_f;
            float e   = exp2f(NLOG2E * arg * arg);      // distinct per lane -> MUFU 1x
            unsigned int eu = __float_as_uint(e);
            ull e2;
            asm("mov.b64 %0, {%1, %1};" : "=l"(e2) : "r"(eu));
            const char* pp = sPb + __float_as_int(mm.y);
            ull pA = ((const ull*)pp)[0];
            ull pB = ((const ull*)pp)[1];
            ull pC = ((const ull*)pp)[2];
            ull pD = ((const ull*)pp)[3];
            asm("fma.rn.f32x2 %0, %1, %2, %0;" : "+l"(acc0) : "l"(e2), "l"(pA));
            asm("fma.rn.f32x2 %0, %1, %2, %0;" : "+l"(acc1) : "l"(e2), "l"(pB));
            asm("fma.rn.f32x2 %0, %1, %2, %0;" : "+l"(acc2) : "l"(e2), "l"(pC));
            asm("fma.rn.f32x2 %0, %1, %2, %0;" : "+l"(acc3) : "l"(e2), "l"(pD));
        }
    }

    // n_norm: robust to int32 or float32 encoding
    int nv = *n_norm_p;
    float nf = (nv > 0 && nv < (1 << 26)) ? (float)nv : __int_as_float(nv);
    const float scale = rsqrtf(nf);

    // Unpack + butterfly-reduce over all 32 lanes (sums over b4 and c_off)
    float l0, h0, l1, h1, l2, h2, l3, h3;
    asm("mov.b64 {%0, %1}, %2;" : "=r"(*(unsigned*)&l0), "=r"(*(unsigned*)&h0) : "l"(acc0));
    asm("mov.b64 {%0, %1}, %2;" : "=r"(*(unsigned*)&l1), "=r"(*(unsigned*)&h1) : "l"(acc1));
    asm("mov.b64 {%0, %1}, %2;" : "=r"(*(unsigned*)&l2), "=r"(*(unsigned*)&h2) : "l"(acc2));
    asm("mov.b64 {%0, %1}, %2;" : "=r"(*(unsigned*)&l3), "=r"(*(unsigned*)&h3) : "l"(acc3));
    #pragma unroll
    for (int off = 16; off; off >>= 1) {
        l0 += __shfl_xor_sync(~0u, l0, off);  h0 += __shfl_xor_sync(~0u, h0, off);
        l1 += __shfl_xor_sync(~0u, l1, off);  h1 += __shfl_xor_sync(~0u, h1, off);
        l2 += __shfl_xor_sync(~0u, l2, off);  h2 += __shfl_xor_sync(~0u, h2, off);
        l3 += __shfl_xor_sync(~0u, l3, off);  h3 += __shfl_xor_sync(~0u, h3, off);
    }

    if (lane == 0) {
        float* row = out + (size_t)(z * N + a0 + w) * 8;
        #define RED(p, v) asm volatile("red.global.add.f32 [%0], %1;" :: "l"(p), "f"(v) : "memory")
        RED(row + 0, l0 * scale);  RED(row + 1, h0 * scale);
        RED(row + 2, l1 * scale);  RED(row + 3, h1 * scale);
        RED(row + 4, l2 * scale);  RED(row + 5, h2 * scale);
        RED(row + 6, l3 * scale);  RED(row + 7, h3 * scale);
        #undef RED
    }
}

extern "C" void kernel_launch(void* const* d_in, const int* in_sizes, int n_in,
                              void* d_out, int out_size)
{
    const float* features = (const float*)d_in[0];   // [B,N,8]
    const float* geometry = (const float*)d_in[1];   // [B,N,3]
    const float* Wm       = (const float*)d_in[2];   // [32,8,8]
    const int*   n_norm   = (const int*)d_in[3];     // scalar

    const int N = NPT;
    const int B = in_sizes[1] / (3 * N);

    float* P;
    cudaGetSymbolAddress((void**)&P, g_P);

    // zero output (red.global.add epilogue accumulates into it)
    cudaMemsetAsync(d_out, 0, (size_t)out_size * sizeof(float));

    compute_P_kernel<<<B * N, 256>>>(features, Wm, P);

    dim3 grid(N / TA, B, NSPLIT);
    conv_window_kernel<<<grid, NTHREADS>>>(geometry, P, n_norm, (float*)d_out, N);
}

// round 7
// speedup vs baseline: 1.7700x; 1.7700x over previous
#include <cuda_runtime.h>
#include <cuda_bf16.h>

// Problem constants (fixed by setup_inputs): B=2, N=1024, D_IN=D_OUT=8, C=32
#define NPT   1024
#define NC    32
#define TA    16        // a's per block (one warp per a)
#define TB    32        // b-tile per smem stage
#define NSPLIT 2        // b-range split for occupancy
#define BRANGE (NPT / NSPLIT)
#define NTHREADS 512
#define CW    8         // c-window width

typedef unsigned long long ull;

// Scratch: pre-contracted P[z][b][c][i], i fastest. Up to 4 batches.
__device__ float g_P[4 * NPT * NC * 8];

// ---------------------------------------------------------------------------
// Kernel 1: P[z,b,c,i] = sum_j W[c,i,j] * feat[z,b,j]
// ---------------------------------------------------------------------------
__global__ __launch_bounds__(256, 4)
void compute_P_kernel(const float* __restrict__ features,  // [B,N,8]
                      const float* __restrict__ Wm,        // [32,8,8]
                      float* __restrict__ P)
{
    __shared__ float sW[NC * 64];
    __shared__ float sf[8];
    const int zb  = blockIdx.x;
    const int tid = threadIdx.x;

    for (int i = tid; i < NC * 64; i += 256) sW[i] = Wm[i];
    if (tid < 8) sf[tid] = features[zb * 8 + tid];
    __syncthreads();

    const int c = tid >> 3, i = tid & 7;
    const float* wr = &sW[c * 64 + i * 8];
    float p = 0.0f;
    #pragma unroll
    for (int j = 0; j < 8; j++) p += wr[j] * sf[j];
    P[(size_t)zb * 256 + tid] = p;
}

// ---------------------------------------------------------------------------
// Kernel 2: windowed radial conv over a b-subrange, red.global.add epilogue.
// Block = (z, 16 a's, b-half). Warp = one a.
// Lane = c_off(lane>>2, 8 values) x ipair(lane&3, 4 values): the 32 lanes of a
// warp read ONE pair's 256B window CONTIGUOUSLY (conflict-free, 2 wavefronts).
// ---------------------------------------------------------------------------
__global__ __launch_bounds__(NTHREADS, 2)
void conv_window_kernel(const float* __restrict__ geometry,  // [B,N,3]
                        const float* __restrict__ P,         // [B,N,32,8]
                        const int*   __restrict__ n_norm_p,
                        float* __restrict__ out,             // [B,N,8]
                        int N)
{
    __shared__ float  s_P[TB * 256];        // 32 KB: P tile [b][c][i]
    __shared__ float2 s_meta[TA * TB];      // {t - c0f, int_as_float(b*1024 + c0*32)}

    const int tid   = threadIdx.x;
    const int w     = tid >> 5;              // warp = a_local
    const int lane  = tid & 31;
    const int z     = blockIdx.y;
    const int a0    = blockIdx.x * TA;
    const int bbase = blockIdx.z * BRANGE;

    const float inv_width = (float)(NC - 1) / 3.5f;
    const float coff_f    = (float)(lane >> 2);       // window-center offset
    const float NLOG2E    = -1.4426950408889634f;
    // this lane's byte slot inside a 256B window: c_off*32 + ipair*8
    const char* sPlane = (const char*)s_P + (lane >> 2) * 32 + (lane & 3) * 8;

    const float* geomz = geometry + (size_t)z * N * 3;
    const float* Pz    = P + (size_t)z * N * 256;

    // Meta-pass identity: thread = pair (am = tid>>5, bb = tid&31)
    const int am = tid >> 5;
    const int bb = tid & 31;
    const float ax = geomz[(a0 + am) * 3 + 0];
    const float ay = geomz[(a0 + am) * 3 + 1];
    const float az = geomz[(a0 + am) * 3 + 2];

    ull accA = 0ull, accB = 0ull;            // two independent f32x2 chains

    for (int t0 = 0; t0 < BRANGE; t0 += TB) {
        __syncthreads();   // previous tile fully consumed

        // Stage P tile: TB*256 floats = 2048 float4, 4 per thread
        {
            const float4* src = (const float4*)(Pz + (size_t)(bbase + t0) * 256);
            float4* dst = (float4*)s_P;
            #pragma unroll
            for (int k = 0; k < 4; k++)
                dst[tid + k * NTHREADS] = src[tid + k * NTHREADS];
        }
        // Meta: one (a,b) pair per thread
        {
            const int bg = bbase + t0 + bb;
            float dx = ax - __ldg(&geomz[bg * 3 + 0]);
            float dy = ay - __ldg(&geomz[bg * 3 + 1]);
            float dz = az - __ldg(&geomz[bg * 3 + 2]);
            float d  = sqrtf(dx * dx + dy * dy + dz * dz + 1e-12f);
            float t  = d * inv_width;
            float c0f = fmaxf(fminf(floorf(t) - 3.0f, (float)(NC - CW)), 0.0f);
            int   off = bb * 1024 + (int)c0f * 32;
            s_meta[am * TB + bb] = make_float2(t - c0f, __int_as_float(off));
        }
        __syncthreads();

        // Hot loop: this warp's a; one pair per step, 2 pairs per iteration
        const float4* m4 = (const float4*)(s_meta + w * TB);   // 2 b's per float4
        #pragma unroll 8
        for (int b2 = 0; b2 < TB / 2; b2++) {
            float4 mm = m4[b2];                       // uniform LDS.128 (broadcast)

            float argA = mm.x - coff_f;
            float eA   = exp2f(NLOG2E * argA * argA); // FMUL,FMUL,MUFU
            unsigned int euA = __float_as_uint(eA);
            ull e2A;
            asm("mov.b64 %0, {%1, %1};" : "=l"(e2A) : "r"(euA));
            ull pA = *(const ull*)(sPlane + __float_as_int(mm.y));
            asm("fma.rn.f32x2 %0, %1, %2, %0;" : "+l"(accA) : "l"(e2A), "l"(pA));

            float argB = mm.z - coff_f;
            float eB   = exp2f(NLOG2E * argB * argB);
            unsigned int euB = __float_as_uint(eB);
            ull e2B;
            asm("mov.b64 %0, {%1, %1};" : "=l"(e2B) : "r"(euB));
            ull pB = *(const ull*)(sPlane + __float_as_int(mm.w));
            asm("fma.rn.f32x2 %0, %1, %2, %0;" : "+l"(accB) : "l"(e2B), "l"(pB));
        }
    }

    // n_norm: robust to int32 or float32 encoding
    int nv = *n_norm_p;
    float nf = (nv > 0 && nv < (1 << 26)) ? (float)nv : __int_as_float(nv);
    const float scale = rsqrtf(nf);

    // Combine chains, unpack, reduce over the 8 c_off lanes per ipair class
    ull acc;
    asm("add.rn.f32x2 %0, %1, %2;" : "=l"(acc) : "l"(accA), "l"(accB));
    unsigned int lou, hiu;
    asm("mov.b64 {%0, %1}, %2;" : "=r"(lou), "=r"(hiu) : "l"(acc));
    float lo = __uint_as_float(lou), hi = __uint_as_float(hiu);
    #pragma unroll
    for (int off = 4; off < 32; off <<= 1) {
        lo += __shfl_xor_sync(0xffffffffu, lo, off);
        hi += __shfl_xor_sync(0xffffffffu, hi, off);
    }

    if (lane < 4) {
        float* row = out + (size_t)(z * N + a0 + w) * 8 + lane * 2;
        asm volatile("red.global.add.f32 [%0], %1;" :: "l"(row),     "f"(lo * scale) : "memory");
        asm volatile("red.global.add.f32 [%0], %1;" :: "l"(row + 1), "f"(hi * scale) : "memory");
    }
}

extern "C" void kernel_launch(void* const* d_in, const int* in_sizes, int n_in,
                              void* d_out, int out_size)
{
    const float* features = (const float*)d_in[0];   // [B,N,8]
    const float* geometry = (const float*)d_in[1];   // [B,N,3]
    const float* Wm       = (const float*)d_in[2];   // [32,8,8]
    const int*   n_norm   = (const int*)d_in[3];     // scalar

    const int N = NPT;
    const int B = in_sizes[1] / (3 * N);

    float* P;
    cudaGetSymbolAddress((void**)&P, g_P);

    // zero output (red.global.add epilogue accumulates into it)
    cudaMemsetAsync(d_out, 0, (size_t)out_size * sizeof(float));

    compute_P_kernel<<<B * N, 256>>>(features, Wm, P);

    dim3 grid(N / TA, B, NSPLIT);
    conv_window_kernel<<<grid, NTHREADS>>>(geometry, P, n_norm, (float*)d_out, N);
}